// round 2
// baseline (speedup 1.0000x reference)
#include <cuda_runtime.h>
#include <math.h>

// Problem constants (from reference setup_inputs)
#define BATCH   32
#define SEQ     12
#define FEAT    128
#define KHEADS  8
#define HDIM    64
#define CDIM    64
#define NNODE   512
#define NCHUNK  8                 // chunks over the n dimension of Wf
#define WF_COLS (NNODE * CDIM)    // 32768 columns per Wf row

// Scratch for partial Wf reduction: [chunk][c'][c]  (8*64*64 floats = 128 KB)
__device__ float g_wf_partial[NCHUNK * CDIM * CDIM];

// ---------------------------------------------------------------------------
// Kernel 1: partial reduction of Wf.
// Wf is (64, 32768) row-major; Wf_sum[c'][c] = sum_n Wf[c', n*64 + c].
// Grid: (NCHUNK, 64). Each block reduces 64 n-values of one c' row chunk
// into 64 per-c partial sums. Fully coalesced float4 loads.
// ---------------------------------------------------------------------------
__global__ void wf_reduce_kernel(const float* __restrict__ Wf) {
    const int chunk = blockIdx.x;   // 0..7
    const int cp    = blockIdx.y;   // 0..63 (c')
    const int t     = threadIdx.x;  // 0..255
    const int c4    = t & 15;       // which group of 4 c-columns (float4)
    const int g     = t >> 4;       // 0..15: n-subgroup

    // Chunk region within this row: 64 n values * 64 c = 4096 floats = 1024 float4
    const float4* row = reinterpret_cast<const float4*>(
        Wf + (size_t)cp * WF_COLS + (size_t)chunk * (64 * CDIM));

    float4 s = make_float4(0.f, 0.f, 0.f, 0.f);
#pragma unroll
    for (int j = 0; j < 4; j++) {
        const int nl = g * 4 + j;           // local n (0..63)
        float4 v = row[nl * 16 + c4];       // n row = 16 float4
        s.x += v.x; s.y += v.y; s.z += v.z; s.w += v.w;
    }

    __shared__ float4 red[256];
    red[t] = s;
    __syncthreads();
    // Tree-reduce the 16 n-subgroups per c4 (offsets keep c4 alignment).
#pragma unroll
    for (int off = 128; off >= 16; off >>= 1) {
        if (t < off) {
            float4 a = red[t], bv = red[t + off];
            a.x += bv.x; a.y += bv.y; a.z += bv.z; a.w += bv.w;
            red[t] = a;
        }
        __syncthreads();
    }
    if (t < 16) {
        float4 a = red[t];
        float* dst = g_wf_partial + ((size_t)chunk * CDIM + cp) * CDIM + t * 4;
        dst[0] = a.x; dst[1] = a.y; dst[2] = a.z; dst[3] = a.w;
    }
}

// ---------------------------------------------------------------------------
// Kernel 2: per-batch pipeline (one block per batch, 512 threads).
//   x_last -> Wh (K*H=512 dots of length 128) -> elu -> h_cat
//   Wh_o[c] = sum_f h_cat[f] * W_out[f][c]   (64 dots of length 512)
//   Wf_sum   = reduce 8 chunk partials (into padded smem, stride 65)
//   out[b][c'] = bf[c'] + sum_c Wh_o[c] * Wf_sum[c'][c]
// All reduction orders fixed -> deterministic.
// ---------------------------------------------------------------------------
__global__ __launch_bounds__(512) void batch_kernel(
    const float* __restrict__ x,
    const float* __restrict__ W_heads,
    const float* __restrict__ W_out,
    const float* __restrict__ bf,
    float* __restrict__ out)
{
    const int b = blockIdx.x;
    const int t = threadIdx.x;  // 0..511

    __shared__ float s_x[FEAT];
    __shared__ float s_hcat[KHEADS * HDIM];   // 512
    __shared__ float s_who[CDIM];
    __shared__ float s_red[512];
    __shared__ float s_wfsum[CDIM * 65];      // padded stride 65 (bank-conflict free)

    if (t < FEAT)
        s_x[t] = x[((size_t)b * SEQ + (SEQ - 1)) * FEAT + t];
    __syncthreads();

    // ---- Wh = x_last @ W_heads, then elu -> h_cat -------------------------
    {
        const int k = t >> 6;       // head
        const int h = t & 63;
        const float* wp = W_heads + (size_t)k * FEAT * HDIM + h;
        float acc = 0.f;
#pragma unroll 16
        for (int f = 0; f < FEAT; f++)
            acc += s_x[f] * wp[f * HDIM];   // coalesced: consecutive h per warp
        s_hcat[t] = (acc > 0.f) ? acc : expm1f(acc);   // elu, alpha=1
    }

    // ---- finish Wf_sum from chunk partials (independent of s_hcat) --------
    {
#pragma unroll
        for (int i = 0; i < 8; i++) {
            const int m = t + 512 * i;      // 0..4095 : flat (c', c)
            float sum = 0.f;
#pragma unroll
            for (int ch = 0; ch < NCHUNK; ch++)
                sum += g_wf_partial[ch * (CDIM * CDIM) + m];
            const int cp = m >> 6, c = m & 63;
            s_wfsum[cp * 65 + c] = sum;
        }
    }
    __syncthreads();

    // ---- Wh_o = h_cat @ W_out ---------------------------------------------
    {
        const int c = t & 63;
        const int g = t >> 6;       // 0..7
        float acc = 0.f;
#pragma unroll
        for (int j = 0; j < 64; j++) {
            const int f = g + 8 * j;
            acc += s_hcat[f] * W_out[f * CDIM + c];   // coalesced over c
        }
        s_red[t] = acc;
    }
    __syncthreads();
    if (t < 64) {
        float acc = 0.f;
#pragma unroll
        for (int g = 0; g < 8; g++)
            acc += s_red[t + 64 * g];
        s_who[t] = acc;
    }
    __syncthreads();

    // ---- final: out[b][c'] = bf[c'] + <Wh_o, Wf_sum[c',:]> ----------------
    if (t < 64) {
        float acc = bf[t];
#pragma unroll
        for (int c = 0; c < 64; c++)
            acc += s_who[c] * s_wfsum[t * 65 + c];    // stride-65: conflict-free
        out[(size_t)b * CDIM + t] = acc;
    }
}

// ---------------------------------------------------------------------------
// Launch. Inputs (metadata order):
//   0: x (32*12*128)  1: W_heads (8*128*64)  2: a1_heads  3: a2_heads
//   4: W_out (512*64) 5: a1_out  6: a2_out   7: Wf (64*32768)  8: bf (64)
// a1/a2 are mathematically dead (attention is exactly uniform).
// Output: float32, 32*64.
// ---------------------------------------------------------------------------
extern "C" void kernel_launch(void* const* d_in, const int* in_sizes, int n_in,
                              void* d_out, int out_size) {
    const float* x       = (const float*)d_in[0];
    const float* W_heads = (const float*)d_in[1];
    const float* W_out   = (const float*)d_in[4];
    const float* Wf      = (const float*)d_in[7];
    const float* bf      = (const float*)d_in[8];
    float* out = (float*)d_out;

    dim3 g1(NCHUNK, CDIM);               // 512 blocks
    wf_reduce_kernel<<<g1, 256>>>(Wf);
    batch_kernel<<<BATCH, 512>>>(x, W_heads, W_out, bf, out);
}

// round 3
// speedup vs baseline: 1.2944x; 1.2944x over previous
#include <cuda_runtime.h>
#include <math.h>

#define BATCH   32
#define SEQ     12
#define FEAT    128
#define KHEADS  8
#define HDIM    64
#define CDIM    64
#define NNODE   512
#define WF_COLS (NNODE * CDIM)    // 32768 floats per Wf row

// Per-batch Wh_o vectors: [32][64]
__device__ float g_who[BATCH * CDIM];

// ---------------------------------------------------------------------------
// K1: per-batch  Wh = x_last @ W_heads -> elu -> h_cat ;  Wh_o = h_cat @ W_out
// One block per batch, 512 threads, all global loads are float4.
// (Attention blocks are mathematically identity: all nodes identical ->
//  softmax exactly uniform -> att @ Wh == Wh. a1/a2 are dead inputs.)
// ---------------------------------------------------------------------------
__global__ __launch_bounds__(512) void who_kernel(
    const float* __restrict__ x,
    const float* __restrict__ W_heads,   // (K, F, H) = (8,128,64), h contiguous
    const float* __restrict__ W_out,     // (K*H, C) = (512,64), c contiguous
    float* __restrict__ who)             // (32,64)
{
    const int b = blockIdx.x;
    const int t = threadIdx.x;

    __shared__ float  s_x[FEAT];
    __shared__ float4 red[512];          // 8 KB reduction scratch
    __shared__ float  s_h[KHEADS * HDIM];// 512 floats: elu(h_cat)

    if (t < FEAT)
        s_x[t] = x[((size_t)b * SEQ + (SEQ - 1)) * FEAT + t];
    __syncthreads();

    // ---- Wh: 128 (k,h4) float4-outputs, 4 threads split the f-dim ----------
    {
        const int p   = t >> 2;          // 0..127 : p = k*16 + h4
        const int sub = t & 3;           // f-quarter
        const int k   = p >> 4;
        const int h4  = p & 15;
        const float4* W = reinterpret_cast<const float4*>(W_heads);
        float4 acc = make_float4(0.f, 0.f, 0.f, 0.f);
        const int f0 = sub * 32;
#pragma unroll
        for (int j = 0; j < 32; j++) {
            const int f = f0 + j;
            const float xv = s_x[f];
            const float4 w = W[(k * FEAT + f) * 16 + h4];
            acc.x += xv * w.x; acc.y += xv * w.y;
            acc.z += xv * w.z; acc.w += xv * w.w;
        }
        red[t] = acc;
    }
    __syncthreads();
    if (t < 128) {
        // sum the 4 f-quarters of pair p = t; note flat h_cat index = t*4+comp
        float4 a = red[4 * t], b1 = red[4 * t + 1], c1 = red[4 * t + 2], d = red[4 * t + 3];
        float v0 = a.x + b1.x + c1.x + d.x;
        float v1 = a.y + b1.y + c1.y + d.y;
        float v2 = a.z + b1.z + c1.z + d.z;
        float v3 = a.w + b1.w + c1.w + d.w;
        s_h[4 * t + 0] = (v0 > 0.f) ? v0 : expm1f(v0);
        s_h[4 * t + 1] = (v1 > 0.f) ? v1 : expm1f(v1);
        s_h[4 * t + 2] = (v2 > 0.f) ? v2 : expm1f(v2);
        s_h[4 * t + 3] = (v3 > 0.f) ? v3 : expm1f(v3);
    }
    __syncthreads();

    // ---- Wh_o: 16 c-float4 outputs, 32 thread-groups split the 512 f-dim ---
    {
        const int c4  = t & 15;
        const int grp = t >> 4;          // 0..31, 16 f each
        const float4* Wo = reinterpret_cast<const float4*>(W_out);
        float4 acc = make_float4(0.f, 0.f, 0.f, 0.f);
#pragma unroll
        for (int j = 0; j < 16; j++) {
            const int f = grp * 16 + j;
            const float hv = s_h[f];
            const float4 w = Wo[f * 16 + c4];
            acc.x += hv * w.x; acc.y += hv * w.y;
            acc.z += hv * w.z; acc.w += hv * w.w;
        }
        red[t] = acc;
    }
    __syncthreads();
#pragma unroll
    for (int off = 256; off >= 16; off >>= 1) {
        if (t < off) {
            float4 a = red[t], bv = red[t + off];
            a.x += bv.x; a.y += bv.y; a.z += bv.z; a.w += bv.w;
            red[t] = a;
        }
        __syncthreads();
    }
    if (t < 16)
        reinterpret_cast<float4*>(who)[b * 16 + t] = red[t];
}

// ---------------------------------------------------------------------------
// K2: one block per output channel c'.  Stream the 128 KB Wf row (float4,
// MLP=16/thread), tree-reduce to Wf_sum[c',:] (64 floats), then fuse the
// final GEMV: out[b][c'] = bf[c'] + <who[b,:], Wf_sum[c',:]> for all 32 b.
// who is staged into smem with stride-65 padding (conflict-free final dot).
// ---------------------------------------------------------------------------
__global__ __launch_bounds__(512) void wf_out_kernel(
    const float* __restrict__ Wf,        // (64, 32768)
    const float* __restrict__ who,       // (32, 64)
    const float* __restrict__ bf,        // (64)
    float* __restrict__ out)             // (32, 64)
{
    const int cp = blockIdx.x;           // c' : 0..63
    const int t  = threadIdx.x;

    __shared__ float4 red[512];
    __shared__ float  s_wf[CDIM];
    __shared__ float  s_who[BATCH * 65]; // padded: bank-conflict-free

    // stage who (8 KB) — overlaps with the Wf row stream below
#pragma unroll
    for (int i = t; i < BATCH * CDIM; i += 512)
        s_who[(i >> 6) * 65 + (i & 63)] = who[i];

    // stream & partially reduce one Wf row: thread handles c4 = t&15, 16 n's
    {
        const float4* row = reinterpret_cast<const float4*>(
            Wf + (size_t)cp * WF_COLS);
        const int c4  = t & 15;
        const int grp = t >> 4;          // 0..31, each covers 16 of 512 n
        float4 acc = make_float4(0.f, 0.f, 0.f, 0.f);
#pragma unroll
        for (int j = 0; j < 16; j++) {
            const int n = grp * 16 + j;
            const float4 v = row[n * 16 + c4];
            acc.x += v.x; acc.y += v.y; acc.z += v.z; acc.w += v.w;
        }
        red[t] = acc;
    }
    __syncthreads();
#pragma unroll
    for (int off = 256; off >= 16; off >>= 1) {
        if (t < off) {
            float4 a = red[t], bv = red[t + off];
            a.x += bv.x; a.y += bv.y; a.z += bv.z; a.w += bv.w;
            red[t] = a;
        }
        __syncthreads();
    }
    if (t < 16) {
        const float4 a = red[t];
        s_wf[4 * t + 0] = a.x; s_wf[4 * t + 1] = a.y;
        s_wf[4 * t + 2] = a.z; s_wf[4 * t + 3] = a.w;
    }
    __syncthreads();

    // fused final GEMV for this channel
    if (t < BATCH) {
        const int b = t;
        float acc = bf[cp];
#pragma unroll
        for (int c = 0; c < CDIM; c++)
            acc += s_who[b * 65 + c] * s_wf[c];   // s_wf[c] broadcast
        out[(size_t)b * CDIM + cp] = acc;
    }
}

// ---------------------------------------------------------------------------
// Inputs (metadata order): 0:x 1:W_heads 2:a1_heads 3:a2_heads 4:W_out
// 5:a1_out 6:a2_out 7:Wf 8:bf.  a1*/a2* are dead (attention exactly uniform).
// ---------------------------------------------------------------------------
extern "C" void kernel_launch(void* const* d_in, const int* in_sizes, int n_in,
                              void* d_out, int out_size) {
    const float* x       = (const float*)d_in[0];
    const float* W_heads = (const float*)d_in[1];
    const float* W_out   = (const float*)d_in[4];
    const float* Wf      = (const float*)d_in[7];
    const float* bf      = (const float*)d_in[8];
    float* out = (float*)d_out;

    who_kernel<<<BATCH, 512>>>(x, W_heads, W_out, g_who);
    wf_out_kernel<<<CDIM, 512>>>(Wf, g_who, bf, out);
}

// round 4
// speedup vs baseline: 1.6523x; 1.2765x over previous
#include <cuda_runtime.h>
#include <math.h>

#define BATCH   32
#define SEQ     12
#define FEAT    128
#define KHEADS  8
#define HDIM    64
#define CDIM    64
#define NNODE   512
#define WF_COLS (NNODE * CDIM)    // 32768 floats per Wf row

// Inter-block handshake state (zero-initialized; reset at end of each launch)
__device__ float    g_who[BATCH * CDIM];
__device__ unsigned g_ready;     // producers completed (0..32)
__device__ unsigned g_done;      // consumers completed (0..64)

// ---------------------------------------------------------------------------
// Single fused kernel, 96 blocks x 512 threads (one wave on 148 SMs):
//   blocks 0..31  : producer — who[b] = elu(x_last @ W_heads) @ W_out
//   blocks 32..95 : consumer — reduce Wf row c' (overlapped with producers),
//                   wait for who, emit out[:, c'] fused.
// Attention blocks are exactly identity (all N nodes identical -> softmax
// uniform -> att @ Wh == Wh); a1*/a2* inputs are mathematically dead.
// ---------------------------------------------------------------------------
__global__ __launch_bounds__(512) void fused_kernel(
    const float* __restrict__ x,         // (32,12,128)
    const float* __restrict__ W_heads,   // (8,128,64)
    const float* __restrict__ W_out,     // (512,64)
    const float* __restrict__ Wf,        // (64,32768)
    const float* __restrict__ bf,        // (64)
    float* __restrict__ out)             // (32,64)
{
    const int t = threadIdx.x;

    __shared__ float4 red[512];          // 8 KB reduction scratch

    if (blockIdx.x < BATCH) {
        // =================== producer: who[b] ===========================
        const int b = blockIdx.x;
        __shared__ float s_x[FEAT];
        __shared__ float s_h[KHEADS * HDIM];

        if (t < FEAT)
            s_x[t] = x[((size_t)b * SEQ + (SEQ - 1)) * FEAT + t];
        __syncthreads();

        // Wh: 128 (k,h4) float4 outputs, 4 threads split the f dimension
        {
            const int p   = t >> 2;      // k*16 + h4
            const int sub = t & 3;
            const int k   = p >> 4;
            const int h4  = p & 15;
            const float4* W = reinterpret_cast<const float4*>(W_heads);
            float4 acc = make_float4(0.f, 0.f, 0.f, 0.f);
            const int f0 = sub * 32;
#pragma unroll
            for (int j = 0; j < 32; j++) {
                const int f = f0 + j;
                const float xv = s_x[f];
                const float4 w = W[(k * FEAT + f) * 16 + h4];
                acc.x += xv * w.x; acc.y += xv * w.y;
                acc.z += xv * w.z; acc.w += xv * w.w;
            }
            red[t] = acc;
        }
        __syncthreads();
        if (t < 128) {
            float4 a = red[4*t], b1 = red[4*t+1], c1 = red[4*t+2], d = red[4*t+3];
            float v0 = a.x + b1.x + c1.x + d.x;
            float v1 = a.y + b1.y + c1.y + d.y;
            float v2 = a.z + b1.z + c1.z + d.z;
            float v3 = a.w + b1.w + c1.w + d.w;
            s_h[4*t+0] = (v0 > 0.f) ? v0 : expm1f(v0);   // elu
            s_h[4*t+1] = (v1 > 0.f) ? v1 : expm1f(v1);
            s_h[4*t+2] = (v2 > 0.f) ? v2 : expm1f(v2);
            s_h[4*t+3] = (v3 > 0.f) ? v3 : expm1f(v3);
        }
        __syncthreads();

        // Wh_o: 16 c-float4 outputs, 32 groups split the 512 f dimension
        {
            const int c4  = t & 15;
            const int grp = t >> 4;
            const float4* Wo = reinterpret_cast<const float4*>(W_out);
            float4 acc = make_float4(0.f, 0.f, 0.f, 0.f);
#pragma unroll
            for (int j = 0; j < 16; j++) {
                const int f = grp * 16 + j;
                const float hv = s_h[f];
                const float4 w = Wo[f * 16 + c4];
                acc.x += hv * w.x; acc.y += hv * w.y;
                acc.z += hv * w.z; acc.w += hv * w.w;
            }
            red[t] = acc;
        }
        __syncthreads();
#pragma unroll
        for (int off = 256; off >= 16; off >>= 1) {
            if (t < off) {
                float4 a = red[t], bv = red[t + off];
                a.x += bv.x; a.y += bv.y; a.z += bv.z; a.w += bv.w;
                red[t] = a;
            }
            __syncthreads();
        }
        if (t < 16)
            reinterpret_cast<float4*>(g_who)[b * 16 + t] = red[t];
        __syncthreads();
        if (t == 0) {
            __threadfence();                 // release g_who (cumulative)
            atomicAdd(&g_ready, 1u);
        }
    } else {
        // =================== consumer: Wf row c' ========================
        const int cp = blockIdx.x - BATCH;   // 0..63
        __shared__ float s_wf[CDIM];
        __shared__ float s_who[BATCH * 65];  // padded: conflict-free dot

        // stream + partially reduce 128 KB Wf row (MLP=16 float4 / thread)
        {
            const float4* row = reinterpret_cast<const float4*>(
                Wf + (size_t)cp * WF_COLS);
            const int c4  = t & 15;
            const int grp = t >> 4;
            float4 acc = make_float4(0.f, 0.f, 0.f, 0.f);
#pragma unroll
            for (int j = 0; j < 16; j++) {
                const float4 v = row[(grp * 16 + j) * 16 + c4];
                acc.x += v.x; acc.y += v.y; acc.z += v.z; acc.w += v.w;
            }
            red[t] = acc;
        }
        __syncthreads();
#pragma unroll
        for (int off = 256; off >= 16; off >>= 1) {
            if (t < off) {
                float4 a = red[t], bv = red[t + off];
                a.x += bv.x; a.y += bv.y; a.z += bv.z; a.w += bv.w;
                red[t] = a;
            }
            __syncthreads();
        }
        if (t < 16) {
            const float4 a = red[t];
            s_wf[4*t+0] = a.x; s_wf[4*t+1] = a.y;
            s_wf[4*t+2] = a.z; s_wf[4*t+3] = a.w;
        }

        // wait for producers (leader spins, then block-wide acquire)
        if (t == 0) {
            volatile unsigned* vp = &g_ready;
            while (*vp < BATCH) { __nanosleep(32); }
            __threadfence();                 // acquire g_who (cumulative)
        }
        __syncthreads();

        // stage who into padded smem (coalesced)
#pragma unroll
        for (int i = t; i < BATCH * CDIM; i += 512)
            s_who[(i >> 6) * 65 + (i & 63)] = g_who[i];
        __syncthreads();

        // fused final GEMV for this channel
        if (t < BATCH) {
            float acc = bf[cp];
#pragma unroll
            for (int c = 0; c < CDIM; c++)
                acc += s_who[t * 65 + c] * s_wf[c];
            out[(size_t)t * CDIM + cp] = acc;
        }
        __syncthreads();

        // last consumer resets handshake state for the next replay
        if (t == 0) {
            unsigned old = atomicAdd(&g_done, 1u);
            if (old == CDIM - 1) {
                g_ready = 0u;
                __threadfence();
                g_done = 0u;
            }
        }
    }
}

// ---------------------------------------------------------------------------
// Inputs (metadata order): 0:x 1:W_heads 2:a1_heads 3:a2_heads 4:W_out
// 5:a1_out 6:a2_out 7:Wf 8:bf.  Output float32 (32,64).
// ---------------------------------------------------------------------------
extern "C" void kernel_launch(void* const* d_in, const int* in_sizes, int n_in,
                              void* d_out, int out_size) {
    const float* x       = (const float*)d_in[0];
    const float* W_heads = (const float*)d_in[1];
    const float* W_out   = (const float*)d_in[4];
    const float* Wf      = (const float*)d_in[7];
    const float* bf      = (const float*)d_in[8];
    float* out = (float*)d_out;

    fused_kernel<<<BATCH + CDIM, 512>>>(x, W_heads, W_out, Wf, bf, out);
}